// round 9
// baseline (speedup 1.0000x reference)
#include <cuda_runtime.h>
#include <cstdint>

// Shapes (fixed):
//   z:     [16, 128, 32, 32] f32   (B=16, C=128=L*D, H=W=32)
//   codes: [8, 512, 16]      f32   (L=8, K=512, D=16)
// d_out (f32): soft[16384*128] | hard[16384*128] | idx[16384*8]

#define KN   512
#define DN   16
#define LN   8
#define NPOS 16384
#define HN   (NPOS * 128)
#define BLKPOS 222               // positions per block (74 blocks/l)
#define GUARD 2e-4f              // ordering-error guard band on d2 top-2 gap

typedef unsigned long long f2;  // packed f32x2

__device__ __forceinline__ f2 pack2(float lo, float hi) {
    f2 r; asm("mov.b64 %0, {%1,%2};" : "=l"(r) : "f"(lo), "f"(hi)); return r;
}
__device__ __forceinline__ void unpack2(f2 v, float& lo, float& hi) {
    asm("mov.b64 {%0,%1}, %2;" : "=f"(lo), "=f"(hi) : "l"(v));
}
__device__ __forceinline__ f2 fma2(f2 a, f2 b, f2 c) {
    f2 d; asm("fma.rn.f32x2 %0, %1, %2, %3;" : "=l"(d) : "l"(a), "l"(b), "l"(c)); return d;
}
__device__ __forceinline__ float sqrt_approx(float x) {
    float r; asm("sqrt.approx.f32 %0, %1;" : "=f"(r) : "f"(x)); return r;
}
__device__ __forceinline__ float expneg_approx(float x) {   // e^{-x}
    float r;
    asm("mul.f32 %0, %1, 0fBFB8AA3B;\n\tex2.approx.f32 %0, %0;" : "=f"(r) : "f"(x));
    return r;
}

// exact d2 in reference order (rescan path only)
__device__ __forceinline__ float d2_exact(const float* __restrict__ h, float h2,
                                          const float* __restrict__ c, float w2) {
    float dot = 0.f;
    #pragma unroll
    for (int d = 0; d < DN; d++) dot = fmaf(h[d], c[d], dot);
    float t = fmaf(-2.0f, dot, h2);   // == fl(h2 - fl(2*dot)), 2*dot exact
    return __fadd_rn(t, w2);
}

__device__ __forceinline__ void finish_pos(
    const float* __restrict__ h, float h2, float best0, float best1, int k0,
    float S, const f2* __restrict__ acc, int n, int l,
    const float* __restrict__ cs, const float* __restrict__ w2s,
    float* __restrict__ out, int out_size)
{
    int bk = k0;
    if (best1 - best0 < GUARD) {
        // close call: rerun the exact reference rule (first index of min fp32 dist)
        float minv = 3.4e38f;
        for (int k = 0; k < KN; k++) {
            float d2 = d2_exact(h, h2, cs + k * DN, w2s[k]);
            float sd = __fsqrt_rn(fmaxf(d2, 1e-12f));
            if (sd < minv) { minv = sd; bk = k; }
        }
    }

    float inv = 1.0f / S;
    float so[DN];
    #pragma unroll
    for (int i = 0; i < 8; i++) unpack2(acc[i], so[2 * i], so[2 * i + 1]);

    float4* o4 = reinterpret_cast<float4*>(out + (size_t)n * 128 + l * DN);
    #pragma unroll
    for (int j = 0; j < 4; j++) {
        float4 v;
        v.x = so[4 * j + 0] * inv;
        v.y = so[4 * j + 1] * inv;
        v.z = so[4 * j + 2] * inv;
        v.w = so[4 * j + 3] * inv;
        o4[j] = v;
    }
    if (out_size >= 2 * HN) {
        const float4* cr = reinterpret_cast<const float4*>(cs + bk * DN);
        float4* ho = reinterpret_cast<float4*>(out + HN + (size_t)n * 128 + l * DN);
        #pragma unroll
        for (int j = 0; j < 4; j++) ho[j] = cr[j];
    }
    if (out_size >= 2 * HN + NPOS * LN) {
        out[2 * HN + (size_t)n * LN + l] = (float)bk;
    }
}

template<bool DO_B>
__device__ __forceinline__ void vq_work(
    int n0, int n1, bool bvalid, int l,
    const float* __restrict__ z,
    const float* __restrict__ cs, const float* __restrict__ w2s,
    float* __restrict__ out, int out_size)
{
    const int n1c = bvalid ? n1 : n0;   // safe index for loads

    float hA[DN], hB[DN];
    {
        const int b0 = n0 >> 10,  s0 = n0 & 1023;
        const float* za = z + (size_t)b0 * (128 * 1024) + (size_t)(l * DN) * 1024 + s0;
        #pragma unroll
        for (int d = 0; d < DN; d++) hA[d] = za[(size_t)d * 1024];
        if (DO_B) {
            const int b1 = n1c >> 10, s1 = n1c & 1023;
            const float* zb = z + (size_t)b1 * (128 * 1024) + (size_t)(l * DN) * 1024 + s1;
            #pragma unroll
            for (int d = 0; d < DN; d++) hB[d] = zb[(size_t)d * 1024];
        }
    }
    float h2A = 0.f, h2B = 0.f;
    #pragma unroll
    for (int d = 0; d < DN; d++) h2A = __fadd_rn(h2A, __fmul_rn(hA[d], hA[d]));
    if (DO_B) {
        #pragma unroll
        for (int d = 0; d < DN; d++) h2B = __fadd_rn(h2B, __fmul_rn(hB[d], hB[d]));
    }

    float bA0 = 3.4e38f, bA1 = 3.4e38f, bB0 = 3.4e38f, bB1 = 3.4e38f;
    int   kA0 = 0, kB0 = 0;
    float SA = 0.f, SB = 0.f;
    f2 accA[8], accB[8];
    #pragma unroll
    for (int i = 0; i < 8; i++) { accA[i] = 0ull; accB[i] = 0ull; }

    const ulonglong2* qp = reinterpret_cast<const ulonglong2*>(cs);

    #pragma unroll 4
    for (int k = 0; k < KN; k++) {
        ulonglong2 A = qp[k * 4 + 0];
        ulonglong2 B = qp[k * 4 + 1];
        ulonglong2 C = qp[k * 4 + 2];
        ulonglong2 D = qp[k * 4 + 3];
        float w2 = w2s[k];

        float q0,q1,q2,q3,q4,q5,q6,q7,q8,q9,q10,q11,q12,q13,q14,q15;
        unpack2(A.x, q0,  q1);  unpack2(A.y, q2,  q3);
        unpack2(B.x, q4,  q5);  unpack2(B.y, q6,  q7);
        unpack2(C.x, q8,  q9);  unpack2(C.y, q10, q11);
        unpack2(D.x, q12, q13); unpack2(D.y, q14, q15);

        // tree dot: 4 independent chains of 4 (approx path; guard covers ordering)
        float a0A = __fmul_rn(hA[0],  q0);
        float a1A = __fmul_rn(hA[4],  q4);
        float a2A = __fmul_rn(hA[8],  q8);
        float a3A = __fmul_rn(hA[12], q12);
        a0A = fmaf(hA[1],  q1,  a0A);
        a1A = fmaf(hA[5],  q5,  a1A);
        a2A = fmaf(hA[9],  q9,  a2A);
        a3A = fmaf(hA[13], q13, a3A);
        a0A = fmaf(hA[2],  q2,  a0A);
        a1A = fmaf(hA[6],  q6,  a1A);
        a2A = fmaf(hA[10], q10, a2A);
        a3A = fmaf(hA[14], q14, a3A);
        a0A = fmaf(hA[3],  q3,  a0A);
        a1A = fmaf(hA[7],  q7,  a1A);
        a2A = fmaf(hA[11], q11, a2A);
        a3A = fmaf(hA[15], q15, a3A);
        float dotA = (a0A + a1A) + (a2A + a3A);
        float d2A = __fadd_rn(fmaf(-2.0f, dotA, h2A), w2);

        float oA = bA0; bool lA = d2A < bA0;
        bA0 = lA ? d2A : bA0;  kA0 = lA ? k : kA0;
        bA1 = fminf(bA1, fmaxf(oA, d2A));

        float wA = expneg_approx(sqrt_approx(fmaxf(d2A, 1e-12f)));
        SA += wA;
        f2 wpA = pack2(wA, wA);
        accA[0] = fma2(wpA, A.x, accA[0]);
        accA[1] = fma2(wpA, A.y, accA[1]);
        accA[2] = fma2(wpA, B.x, accA[2]);
        accA[3] = fma2(wpA, B.y, accA[3]);
        accA[4] = fma2(wpA, C.x, accA[4]);
        accA[5] = fma2(wpA, C.y, accA[5]);
        accA[6] = fma2(wpA, D.x, accA[6]);
        accA[7] = fma2(wpA, D.y, accA[7]);

        if (DO_B) {
            float a0B = __fmul_rn(hB[0],  q0);
            float a1B = __fmul_rn(hB[4],  q4);
            float a2B = __fmul_rn(hB[8],  q8);
            float a3B = __fmul_rn(hB[12], q12);
            a0B = fmaf(hB[1],  q1,  a0B);
            a1B = fmaf(hB[5],  q5,  a1B);
            a2B = fmaf(hB[9],  q9,  a2B);
            a3B = fmaf(hB[13], q13, a3B);
            a0B = fmaf(hB[2],  q2,  a0B);
            a1B = fmaf(hB[6],  q6,  a1B);
            a2B = fmaf(hB[10], q10, a2B);
            a3B = fmaf(hB[14], q14, a3B);
            a0B = fmaf(hB[3],  q3,  a0B);
            a1B = fmaf(hB[7],  q7,  a1B);
            a2B = fmaf(hB[11], q11, a2B);
            a3B = fmaf(hB[15], q15, a3B);
            float dotB = (a0B + a1B) + (a2B + a3B);
            float d2B = __fadd_rn(fmaf(-2.0f, dotB, h2B), w2);

            float oB = bB0; bool lB = d2B < bB0;
            bB0 = lB ? d2B : bB0;  kB0 = lB ? k : kB0;
            bB1 = fminf(bB1, fmaxf(oB, d2B));

            float wB = expneg_approx(sqrt_approx(fmaxf(d2B, 1e-12f)));
            SB += wB;
            f2 wpB = pack2(wB, wB);
            accB[0] = fma2(wpB, A.x, accB[0]);
            accB[1] = fma2(wpB, A.y, accB[1]);
            accB[2] = fma2(wpB, B.x, accB[2]);
            accB[3] = fma2(wpB, B.y, accB[3]);
            accB[4] = fma2(wpB, C.x, accB[4]);
            accB[5] = fma2(wpB, C.y, accB[5]);
            accB[6] = fma2(wpB, D.x, accB[6]);
            accB[7] = fma2(wpB, D.y, accB[7]);
        }
    }

    finish_pos(hA, h2A, bA0, bA1, kA0, SA, accA, n0, l, cs, w2s, out, out_size);
    if (DO_B && bvalid)
        finish_pos(hB, h2B, bB0, bB1, kB0, SB, accB, n1, l, cs, w2s, out, out_size);
}

__global__ __launch_bounds__(128, 4)
void vq_kernel(const float* __restrict__ z,
               const float* __restrict__ codes,
               float* __restrict__ out,
               int out_size)
{
    __shared__ __align__(16) float cs[KN * DN];   // codes[l], [k][d], 32 KB
    __shared__ float w2s[KN];                     // ||codes[l][k]||^2 (ref order)

    const int l = blockIdx.y;
    const int t = threadIdx.x;

    // ---- cooperative load of codes[l] ----
    {
        const float4* cg = reinterpret_cast<const float4*>(codes + (size_t)l * KN * DN);
        float4* cs4 = reinterpret_cast<float4*>(cs);
        #pragma unroll 4
        for (int i = t; i < KN * DN / 4; i += 128) cs4[i] = cg[i];
    }
    __syncthreads();
    for (int k = t; k < KN; k += 128) {
        const float* c = cs + k * DN;
        float a = 0.f;
        #pragma unroll
        for (int d = 0; d < DN; d++) a = __fadd_rn(a, __fmul_rn(c[d], c[d]));
        w2s[k] = a;
    }
    __syncthreads();

    const int base = blockIdx.x * BLKPOS;
    const int n0 = base + t;             // always < NPOS (max 16333)
    const int n1 = base + 128 + t;       // stream B: valid iff t<94 && n1<NPOS
    const bool bvalid = (t < 94) && (n1 < NPOS);

    if (t < 96) {   // warps 0-2: dual stream
        vq_work<true>(n0, n1, bvalid, l, z, cs, w2s, out, out_size);
    } else {        // warp 3: single stream
        vq_work<false>(n0, 0, false, l, z, cs, w2s, out, out_size);
    }
}

extern "C" void kernel_launch(void* const* d_in, const int* in_sizes, int n_in,
                              void* d_out, int out_size) {
    const float* z     = (const float*)d_in[0];
    const float* codes = (const float*)d_in[1];
    float* out = (float*)d_out;

    dim3 grid(74, LN);   // 592 blocks = 148 SMs x 4 CTAs, perfectly balanced
    vq_kernel<<<grid, 128>>>(z, codes, out, out_size);
}

// round 10
// speedup vs baseline: 1.0070x; 1.0070x over previous
#include <cuda_runtime.h>
#include <cstdint>

// Shapes (fixed):
//   z:     [16, 128, 32, 32] f32   (B=16, C=128=L*D, H=W=32)
//   codes: [8, 512, 16]      f32   (L=8, K=512, D=16)
// d_out (f32): soft[16384*128] | hard[16384*128] | idx[16384*8]

#define KN   512
#define DN   16
#define LN   8
#define NPOS 16384
#define HN   (NPOS * 128)
#define BLKPOS 222               // positions per block (74 blocks/l)
#define GUARD 1e-3f              // guard band on approx top-2 d2 gap

typedef unsigned long long f2;  // packed f32x2

__device__ __forceinline__ f2 pack2(float lo, float hi) {
    f2 r; asm("mov.b64 %0, {%1,%2};" : "=l"(r) : "f"(lo), "f"(hi)); return r;
}
__device__ __forceinline__ void unpack2(f2 v, float& lo, float& hi) {
    asm("mov.b64 {%0,%1}, %2;" : "=f"(lo), "=f"(hi) : "l"(v));
}
__device__ __forceinline__ f2 mul2(f2 a, f2 b) {
    f2 d; asm("mul.rn.f32x2 %0, %1, %2;" : "=l"(d) : "l"(a), "l"(b)); return d;
}
__device__ __forceinline__ f2 add2(f2 a, f2 b) {
    f2 d; asm("add.rn.f32x2 %0, %1, %2;" : "=l"(d) : "l"(a), "l"(b)); return d;
}
__device__ __forceinline__ f2 fma2(f2 a, f2 b, f2 c) {
    f2 d; asm("fma.rn.f32x2 %0, %1, %2, %3;" : "=l"(d) : "l"(a), "l"(b), "l"(c)); return d;
}
__device__ __forceinline__ float sqrt_approx(float x) {
    float r; asm("sqrt.approx.f32 %0, %1;" : "=f"(r) : "f"(x)); return r;
}
__device__ __forceinline__ float expneg_approx(float x) {   // e^{-x}
    float r;
    asm("mul.f32 %0, %1, 0fBFB8AA3B;\n\tex2.approx.f32 %0, %0;" : "=f"(r) : "f"(x));
    return r;
}

// exact d2 in reference order (rescan path only)
__device__ __forceinline__ float d2_exact(const float* __restrict__ h, float h2,
                                          const float* __restrict__ c, float w2) {
    float dot = 0.f;
    #pragma unroll
    for (int d = 0; d < DN; d++) dot = fmaf(h[d], c[d], dot);
    float t = fmaf(-2.0f, dot, h2);   // == fl(h2 - fl(2*dot)), 2*dot exact
    return __fadd_rn(t, w2);
}

// finish one position: guard-band argmin resolution + stores
__device__ __forceinline__ void finish_pos(
    const f2* __restrict__ hm, float h2, float best0, float best1, int k0,
    float S, const f2* __restrict__ acc, int n, int l,
    const float* __restrict__ cs, const float* __restrict__ w2s,
    float* __restrict__ out, int out_size)
{
    int bk = k0;
    if (best1 - best0 < GUARD) {
        // close call: rerun exact reference rule (first index of min fp32 dist)
        float hs[DN];
        #pragma unroll
        for (int i = 0; i < 8; i++) {
            float a, b; unpack2(hm[i], a, b);
            hs[2 * i]     = -0.5f * a;   // hm = -2h, so -0.5*hm = h exactly
            hs[2 * i + 1] = -0.5f * b;
        }
        float minv = 3.4e38f;
        for (int k = 0; k < KN; k++) {
            float d2 = d2_exact(hs, h2, cs + k * DN, w2s[k]);
            float sd = __fsqrt_rn(fmaxf(d2, 1e-12f));
            if (sd < minv) { minv = sd; bk = k; }
        }
    }

    float inv = 1.0f / S;
    float so[DN];
    #pragma unroll
    for (int i = 0; i < 8; i++) unpack2(acc[i], so[2 * i], so[2 * i + 1]);

    float4* o4 = reinterpret_cast<float4*>(out + (size_t)n * 128 + l * DN);
    #pragma unroll
    for (int j = 0; j < 4; j++) {
        float4 v;
        v.x = so[4 * j + 0] * inv;
        v.y = so[4 * j + 1] * inv;
        v.z = so[4 * j + 2] * inv;
        v.w = so[4 * j + 3] * inv;
        o4[j] = v;
    }
    if (out_size >= 2 * HN) {
        const float4* cr = reinterpret_cast<const float4*>(cs + bk * DN);
        float4* ho = reinterpret_cast<float4*>(out + HN + (size_t)n * 128 + l * DN);
        #pragma unroll
        for (int j = 0; j < 4; j++) ho[j] = cr[j];
    }
    if (out_size >= 2 * HN + NPOS * LN) {
        out[2 * HN + (size_t)n * LN + l] = (float)bk;
    }
}

template<bool DO_B>
__device__ __forceinline__ void vq_work(
    int n0, int n1, bool bvalid, int l,
    const float* __restrict__ z,
    const float* __restrict__ cs, const float* __restrict__ w2s,
    float* __restrict__ out, int out_size)
{
    const int n1c = bvalid ? n1 : n0;   // safe index for loads

    // load h, compute exact h2, then keep only hm = -2h (packed)
    f2 hmA[8], hmB[8];
    float h2A = 0.f, h2B = 0.f;
    {
        const int b0 = n0 >> 10, s0 = n0 & 1023;
        const float* za = z + (size_t)b0 * (128 * 1024) + (size_t)(l * DN) * 1024 + s0;
        float h[DN];
        #pragma unroll
        for (int d = 0; d < DN; d++) h[d] = za[(size_t)d * 1024];
        #pragma unroll
        for (int d = 0; d < DN; d++) h2A = __fadd_rn(h2A, __fmul_rn(h[d], h[d]));
        #pragma unroll
        for (int i = 0; i < 8; i++) hmA[i] = pack2(-2.f * h[2 * i], -2.f * h[2 * i + 1]);
        if (DO_B) {
            const int b1 = n1c >> 10, s1 = n1c & 1023;
            const float* zb = z + (size_t)b1 * (128 * 1024) + (size_t)(l * DN) * 1024 + s1;
            #pragma unroll
            for (int d = 0; d < DN; d++) h[d] = zb[(size_t)d * 1024];
            #pragma unroll
            for (int d = 0; d < DN; d++) h2B = __fadd_rn(h2B, __fmul_rn(h[d], h[d]));
            #pragma unroll
            for (int i = 0; i < 8; i++) hmB[i] = pack2(-2.f * h[2 * i], -2.f * h[2 * i + 1]);
        }
    }

    float bA0 = 3.4e38f, bA1 = 3.4e38f, bB0 = 3.4e38f, bB1 = 3.4e38f;
    int   kA0 = 0, kB0 = 0;
    float SA = 0.f, SB = 0.f;
    f2 accA[8], accB[8];
    #pragma unroll
    for (int i = 0; i < 8; i++) { accA[i] = 0ull; accB[i] = 0ull; }

    const ulonglong2* qp = reinterpret_cast<const ulonglong2*>(cs);

    #pragma unroll 4
    for (int k = 0; k < KN; k++) {
        ulonglong2 A = qp[k * 4 + 0];
        ulonglong2 B = qp[k * 4 + 1];
        ulonglong2 C = qp[k * 4 + 2];
        ulonglong2 D = qp[k * 4 + 3];
        float w2 = w2s[k];

        // stream A: d2 = (h2 + w2) + sum(-2h .* q), 2 packed chains of 4
        float eA = h2A + w2;
        f2 c0 = mul2(hmA[0], A.x);
        f2 c1 = mul2(hmA[1], A.y);
        c0 = fma2(hmA[2], B.x, c0);
        c1 = fma2(hmA[3], B.y, c1);
        c0 = fma2(hmA[4], C.x, c0);
        c1 = fma2(hmA[5], C.y, c1);
        c0 = fma2(hmA[6], D.x, c0);
        c1 = fma2(hmA[7], D.y, c1);
        c0 = add2(c0, c1);
        float lo, hi; unpack2(c0, lo, hi);
        float d2A = (eA + lo) + hi;

        float oA = bA0; bool lA = d2A < bA0;
        bA0 = lA ? d2A : bA0;  kA0 = lA ? k : kA0;
        bA1 = fminf(bA1, fmaxf(oA, d2A));

        float wA = expneg_approx(sqrt_approx(fmaxf(d2A, 1e-12f)));
        SA += wA;
        f2 wpA = pack2(wA, wA);
        accA[0] = fma2(wpA, A.x, accA[0]);
        accA[1] = fma2(wpA, A.y, accA[1]);
        accA[2] = fma2(wpA, B.x, accA[2]);
        accA[3] = fma2(wpA, B.y, accA[3]);
        accA[4] = fma2(wpA, C.x, accA[4]);
        accA[5] = fma2(wpA, C.y, accA[5]);
        accA[6] = fma2(wpA, D.x, accA[6]);
        accA[7] = fma2(wpA, D.y, accA[7]);

        if (DO_B) {
            float eB = h2B + w2;
            f2 d0 = mul2(hmB[0], A.x);
            f2 d1 = mul2(hmB[1], A.y);
            d0 = fma2(hmB[2], B.x, d0);
            d1 = fma2(hmB[3], B.y, d1);
            d0 = fma2(hmB[4], C.x, d0);
            d1 = fma2(hmB[5], C.y, d1);
            d0 = fma2(hmB[6], D.x, d0);
            d1 = fma2(hmB[7], D.y, d1);
            d0 = add2(d0, d1);
            float lo2, hi2; unpack2(d0, lo2, hi2);
            float d2B = (eB + lo2) + hi2;

            float oB = bB0; bool lB = d2B < bB0;
            bB0 = lB ? d2B : bB0;  kB0 = lB ? k : kB0;
            bB1 = fminf(bB1, fmaxf(oB, d2B));

            float wB = expneg_approx(sqrt_approx(fmaxf(d2B, 1e-12f)));
            SB += wB;
            f2 wpB = pack2(wB, wB);
            accB[0] = fma2(wpB, A.x, accB[0]);
            accB[1] = fma2(wpB, A.y, accB[1]);
            accB[2] = fma2(wpB, B.x, accB[2]);
            accB[3] = fma2(wpB, B.y, accB[3]);
            accB[4] = fma2(wpB, C.x, accB[4]);
            accB[5] = fma2(wpB, C.y, accB[5]);
            accB[6] = fma2(wpB, D.x, accB[6]);
            accB[7] = fma2(wpB, D.y, accB[7]);
        }
    }

    finish_pos(hmA, h2A, bA0, bA1, kA0, SA, accA, n0, l, cs, w2s, out, out_size);
    if (DO_B && bvalid)
        finish_pos(hmB, h2B, bB0, bB1, kB0, SB, accB, n1, l, cs, w2s, out, out_size);
}

__global__ __launch_bounds__(128, 4)
void vq_kernel(const float* __restrict__ z,
               const float* __restrict__ codes,
               float* __restrict__ out,
               int out_size)
{
    __shared__ __align__(16) float cs[KN * DN];   // codes[l], [k][d], 32 KB
    __shared__ float w2s[KN];                     // ||codes[l][k]||^2 (ref order)

    const int l = blockIdx.y;
    const int t = threadIdx.x;

    // ---- cooperative load of codes[l] ----
    {
        const float4* cg = reinterpret_cast<const float4*>(codes + (size_t)l * KN * DN);
        float4* cs4 = reinterpret_cast<float4*>(cs);
        #pragma unroll 4
        for (int i = t; i < KN * DN / 4; i += 128) cs4[i] = cg[i];
    }
    __syncthreads();
    for (int k = t; k < KN; k += 128) {
        const float* c = cs + k * DN;
        float a = 0.f;
        #pragma unroll
        for (int d = 0; d < DN; d++) a = __fadd_rn(a, __fmul_rn(c[d], c[d]));
        w2s[k] = a;
    }
    __syncthreads();

    const int base = blockIdx.x * BLKPOS;
    const int n0 = base + t;             // always < NPOS (max 16333)
    const int n1 = base + 128 + t;       // stream B: valid iff t<94 && n1<NPOS
    const bool bvalid = (t < 94) && (n1 < NPOS);

    if (t < 96) {   // warps 0-2: dual stream
        vq_work<true>(n0, n1, bvalid, l, z, cs, w2s, out, out_size);
    } else {        // warp 3: single stream
        vq_work<false>(n0, 0, false, l, z, cs, w2s, out, out_size);
    }
}

extern "C" void kernel_launch(void* const* d_in, const int* in_sizes, int n_in,
                              void* d_out, int out_size) {
    const float* z     = (const float*)d_in[0];
    const float* codes = (const float*)d_in[1];
    float* out = (float*)d_out;

    dim3 grid(74, LN);   // 592 blocks = 148 SMs x 4 CTAs, perfectly balanced
    vq_kernel<<<grid, 128>>>(z, codes, out, out_size);
}

// round 11
// speedup vs baseline: 1.6084x; 1.5971x over previous
#include <cuda_runtime.h>
#include <cstdint>

// Shapes (fixed):
//   z:     [16, 128, 32, 32] f32   (B=16, C=128=L*D, H=W=32)
//   codes: [8, 512, 16]      f32   (L=8, K=512, D=16)
// d_out (f32): soft[16384*128] | hard[16384*128] | idx[16384*8]

#define KN   512
#define DN   16
#define LN   8
#define NPOS 16384
#define HN   (NPOS * 128)
#define BLKPOS 222               // positions per block (74 blocks/l)

typedef unsigned long long f2;  // packed f32x2

__device__ __forceinline__ f2 pack2(float lo, float hi) {
    f2 r; asm("mov.b64 %0, {%1,%2};" : "=l"(r) : "f"(lo), "f"(hi)); return r;
}
__device__ __forceinline__ void unpack2(f2 v, float& lo, float& hi) {
    asm("mov.b64 {%0,%1}, %2;" : "=f"(lo), "=f"(hi) : "l"(v));
}
__device__ __forceinline__ f2 fma2(f2 a, f2 b, f2 c) {
    f2 d; asm("fma.rn.f32x2 %0, %1, %2, %3;" : "=l"(d) : "l"(a), "l"(b), "l"(c)); return d;
}
__device__ __forceinline__ float sqrt_approx(float x) {
    float r; asm("sqrt.approx.f32 %0, %1;" : "=f"(r) : "f"(x)); return r;
}
__device__ __forceinline__ float expneg_approx(float x) {   // e^{-x}
    float r;
    asm("mul.f32 %0, %1, 0fBFB8AA3B;\n\tex2.approx.f32 %0, %0;" : "=f"(r) : "f"(x));
    return r;
}

// exact d2 in reference order (rescan path only)
__device__ __forceinline__ float d2_exact(const float* __restrict__ h, float h2,
                                          const float* __restrict__ c, float w2) {
    float dot = 0.f;
    #pragma unroll
    for (int d = 0; d < DN; d++) dot = fmaf(h[d], c[d], dot);
    float t = fmaf(-2.0f, dot, h2);   // == fl(h2 - fl(2*dot)), 2*dot exact
    return __fadd_rn(t, w2);
}

__device__ __forceinline__ void finish_pos(
    const float* __restrict__ h, float h2, float best0, float best1, int k0,
    float S, const f2* __restrict__ acc, int n, int l,
    const float* __restrict__ cs, const float* __restrict__ w2s,
    float* __restrict__ out, int out_size)
{
    float sq0 = __fsqrt_rn(fmaxf(best0, 1e-12f));
    float sq1 = __fsqrt_rn(fmaxf(best1, 1e-12f));
    int bk = k0;
    if (sq1 == sq0) {   // plateau tie (rare): exact first-index rule
        for (int k = 0; k < KN; k++) {
            float d2 = d2_exact(h, h2, cs + k * DN, w2s[k]);
            if (__fsqrt_rn(fmaxf(d2, 1e-12f)) == sq0) { bk = k; break; }
        }
    }

    float inv = 1.0f / S;
    float so[DN];
    #pragma unroll
    for (int i = 0; i < 8; i++) unpack2(acc[i], so[2 * i], so[2 * i + 1]);

    float4* o4 = reinterpret_cast<float4*>(out + (size_t)n * 128 + l * DN);
    #pragma unroll
    for (int j = 0; j < 4; j++) {
        float4 v;
        v.x = so[4 * j + 0] * inv;
        v.y = so[4 * j + 1] * inv;
        v.z = so[4 * j + 2] * inv;
        v.w = so[4 * j + 3] * inv;
        o4[j] = v;
    }
    if (out_size >= 2 * HN) {
        const float4* cr = reinterpret_cast<const float4*>(cs + bk * DN);
        float4* ho = reinterpret_cast<float4*>(out + HN + (size_t)n * 128 + l * DN);
        #pragma unroll
        for (int j = 0; j < 4; j++) ho[j] = cr[j];
    }
    if (out_size >= 2 * HN + NPOS * LN) {
        out[2 * HN + (size_t)n * LN + l] = (float)bk;
    }
}

template<bool DO_B>
__device__ __forceinline__ void vq_work(
    int n0, int n1, bool bvalid, int l,
    const float* __restrict__ z,
    const float* __restrict__ cs, const float* __restrict__ w2s,
    float* __restrict__ out, int out_size)
{
    const int n1c = bvalid ? n1 : n0;   // safe index for loads

    float hA[DN], hB[DN];
    {
        const int b0 = n0 >> 10,  s0 = n0 & 1023;
        const float* za = z + (size_t)b0 * (128 * 1024) + (size_t)(l * DN) * 1024 + s0;
        #pragma unroll
        for (int d = 0; d < DN; d++) hA[d] = za[(size_t)d * 1024];
        if (DO_B) {
            const int b1 = n1c >> 10, s1 = n1c & 1023;
            const float* zb = z + (size_t)b1 * (128 * 1024) + (size_t)(l * DN) * 1024 + s1;
            #pragma unroll
            for (int d = 0; d < DN; d++) hB[d] = zb[(size_t)d * 1024];
        }
    }
    float h2A = 0.f, h2B = 0.f;
    #pragma unroll
    for (int d = 0; d < DN; d++) h2A = __fadd_rn(h2A, __fmul_rn(hA[d], hA[d]));
    if (DO_B) {
        #pragma unroll
        for (int d = 0; d < DN; d++) h2B = __fadd_rn(h2B, __fmul_rn(hB[d], hB[d]));
    }

    float bA0 = 3.4e38f, bA1 = 3.4e38f, bB0 = 3.4e38f, bB1 = 3.4e38f;
    int   kA0 = 0, kB0 = 0;
    float SA = 0.f, SB = 0.f;
    f2 accA[8], accB[8];
    #pragma unroll
    for (int i = 0; i < 8; i++) { accA[i] = 0ull; accB[i] = 0ull; }

    const ulonglong2* qp = reinterpret_cast<const ulonglong2*>(cs);

    #pragma unroll 4
    for (int k = 0; k < KN; k++) {
        ulonglong2 A = qp[k * 4 + 0];
        ulonglong2 B = qp[k * 4 + 1];
        ulonglong2 C = qp[k * 4 + 2];
        ulonglong2 D = qp[k * 4 + 3];
        float w2 = w2s[k];

        float q0,q1,q2,q3,q4,q5,q6,q7,q8,q9,q10,q11,q12,q13,q14,q15;
        unpack2(A.x, q0,  q1);  unpack2(A.y, q2,  q3);
        unpack2(B.x, q4,  q5);  unpack2(B.y, q6,  q7);
        unpack2(C.x, q8,  q9);  unpack2(C.y, q10, q11);
        unpack2(D.x, q12, q13); unpack2(D.y, q14, q15);

        // exact sequential dots (reference contraction order)
        float dA = 0.f, dB = 0.f;
        dA = fmaf(hA[0],q0,dA);   if (DO_B) dB = fmaf(hB[0],q0,dB);
        dA = fmaf(hA[1],q1,dA);   if (DO_B) dB = fmaf(hB[1],q1,dB);
        dA = fmaf(hA[2],q2,dA);   if (DO_B) dB = fmaf(hB[2],q2,dB);
        dA = fmaf(hA[3],q3,dA);   if (DO_B) dB = fmaf(hB[3],q3,dB);
        dA = fmaf(hA[4],q4,dA);   if (DO_B) dB = fmaf(hB[4],q4,dB);
        dA = fmaf(hA[5],q5,dA);   if (DO_B) dB = fmaf(hB[5],q5,dB);
        dA = fmaf(hA[6],q6,dA);   if (DO_B) dB = fmaf(hB[6],q6,dB);
        dA = fmaf(hA[7],q7,dA);   if (DO_B) dB = fmaf(hB[7],q7,dB);
        dA = fmaf(hA[8],q8,dA);   if (DO_B) dB = fmaf(hB[8],q8,dB);
        dA = fmaf(hA[9],q9,dA);   if (DO_B) dB = fmaf(hB[9],q9,dB);
        dA = fmaf(hA[10],q10,dA); if (DO_B) dB = fmaf(hB[10],q10,dB);
        dA = fmaf(hA[11],q11,dA); if (DO_B) dB = fmaf(hB[11],q11,dB);
        dA = fmaf(hA[12],q12,dA); if (DO_B) dB = fmaf(hB[12],q12,dB);
        dA = fmaf(hA[13],q13,dA); if (DO_B) dB = fmaf(hB[13],q13,dB);
        dA = fmaf(hA[14],q14,dA); if (DO_B) dB = fmaf(hB[14],q14,dB);
        dA = fmaf(hA[15],q15,dA); if (DO_B) dB = fmaf(hB[15],q15,dB);

        float d2A = __fadd_rn(fmaf(-2.0f, dA, h2A), w2);

        float oA = bA0; bool lA = d2A < bA0;
        bA0 = lA ? d2A : bA0;  kA0 = lA ? k : kA0;
        bA1 = fminf(bA1, fmaxf(oA, d2A));

        float wA = expneg_approx(sqrt_approx(fmaxf(d2A, 1e-12f)));
        SA += wA;
        f2 wpA = pack2(wA, wA);
        accA[0] = fma2(wpA, A.x, accA[0]);
        accA[1] = fma2(wpA, A.y, accA[1]);
        accA[2] = fma2(wpA, B.x, accA[2]);
        accA[3] = fma2(wpA, B.y, accA[3]);
        accA[4] = fma2(wpA, C.x, accA[4]);
        accA[5] = fma2(wpA, C.y, accA[5]);
        accA[6] = fma2(wpA, D.x, accA[6]);
        accA[7] = fma2(wpA, D.y, accA[7]);

        if (DO_B) {
            float d2B = __fadd_rn(fmaf(-2.0f, dB, h2B), w2);

            float oB = bB0; bool lB = d2B < bB0;
            bB0 = lB ? d2B : bB0;  kB0 = lB ? k : kB0;
            bB1 = fminf(bB1, fmaxf(oB, d2B));

            float wB = expneg_approx(sqrt_approx(fmaxf(d2B, 1e-12f)));
            SB += wB;
            f2 wpB = pack2(wB, wB);
            accB[0] = fma2(wpB, A.x, accB[0]);
            accB[1] = fma2(wpB, A.y, accB[1]);
            accB[2] = fma2(wpB, B.x, accB[2]);
            accB[3] = fma2(wpB, B.y, accB[3]);
            accB[4] = fma2(wpB, C.x, accB[4]);
            accB[5] = fma2(wpB, C.y, accB[5]);
            accB[6] = fma2(wpB, D.x, accB[6]);
            accB[7] = fma2(wpB, D.y, accB[7]);
        }
    }

    finish_pos(hA, h2A, bA0, bA1, kA0, SA, accA, n0, l, cs, w2s, out, out_size);
    if (DO_B && bvalid)
        finish_pos(hB, h2B, bB0, bB1, kB0, SB, accB, n1, l, cs, w2s, out, out_size);
}

__global__ __launch_bounds__(128, 4)
void vq_kernel(const float* __restrict__ z,
               const float* __restrict__ codes,
               float* __restrict__ out,
               int out_size)
{
    __shared__ __align__(16) float cs[KN * DN];   // codes[l], [k][d], 32 KB
    __shared__ float w2s[KN];                     // ||codes[l][k]||^2 (ref order)

    const int l = blockIdx.y;
    const int t = threadIdx.x;

    // ---- cooperative load of codes[l] ----
    {
        const float4* cg = reinterpret_cast<const float4*>(codes + (size_t)l * KN * DN);
        float4* cs4 = reinterpret_cast<float4*>(cs);
        #pragma unroll 4
        for (int i = t; i < KN * DN / 4; i += 128) cs4[i] = cg[i];
    }
    __syncthreads();
    for (int k = t; k < KN; k += 128) {
        const float* c = cs + k * DN;
        float a = 0.f;
        #pragma unroll
        for (int d = 0; d < DN; d++) a = __fadd_rn(a, __fmul_rn(c[d], c[d]));
        w2s[k] = a;
    }
    __syncthreads();

    // ---- SMSP load balancing: rotate which warp is the single-stream one ----
    // HW maps warp->SMSP by wid%4. Fixed single-warp (wid==3) starves SMSP 3
    // and saturates SMSPs 0-2. Rotate per CTA so each SMSP averages
    // 3 dual + 1 single warp across the 4 resident CTAs.
    const int wid  = t >> 5;
    const int lane = t & 31;
    const int sw   = blockIdx.x & 3;              // this CTA's single-stream warp
    const int vw   = (wid + 3 - sw) & 3;          // virtual warp: 3 == single
    const int vt   = vw * 32 + lane;              // virtual thread 0..127

    const int base = blockIdx.x * BLKPOS;
    const int n0 = base + vt;            // always < NPOS (max 16333)
    const int n1 = base + 128 + vt;      // stream B: valid iff vt<94 && n1<NPOS
    const bool bvalid = (vt < 94) && (n1 < NPOS);

    if (vt < 96) {   // virtual warps 0-2: dual stream
        vq_work<true>(n0, n1, bvalid, l, z, cs, w2s, out, out_size);
    } else {         // virtual warp 3: single stream
        vq_work<false>(n0, 0, false, l, z, cs, w2s, out, out_size);
    }
}

extern "C" void kernel_launch(void* const* d_in, const int* in_sizes, int n_in,
                              void* d_out, int out_size) {
    const float* z     = (const float*)d_in[0];
    const float* codes = (const float*)d_in[1];
    float* out = (float*)d_out;

    dim3 grid(74, LN);   // 592 blocks = 148 SMs x 4 CTAs, perfectly balanced
    vq_kernel<<<grid, 128>>>(z, codes, out, out_size);
}

// round 12
// speedup vs baseline: 1.7048x; 1.0599x over previous
#include <cuda_runtime.h>
#include <cstdint>

// Shapes (fixed):
//   z:     [16, 128, 32, 32] f32   (B=16, C=128=L*D, H=W=32)
//   codes: [8, 512, 16]      f32   (L=8, K=512, D=16)
// d_out (f32): soft[16384*128] | hard[16384*128] | idx[16384*8]

#define KN   512
#define DN   16
#define LN   8
#define NPOS 16384
#define HN   (NPOS * 128)
#define BLKPOS 222               // positions per block (74 blocks/l)

typedef unsigned long long f2;  // packed f32x2

__device__ __forceinline__ f2 pack2(float lo, float hi) {
    f2 r; asm("mov.b64 %0, {%1,%2};" : "=l"(r) : "f"(lo), "f"(hi)); return r;
}
__device__ __forceinline__ void unpack2(f2 v, float& lo, float& hi) {
    asm("mov.b64 {%0,%1}, %2;" : "=f"(lo), "=f"(hi) : "l"(v));
}
__device__ __forceinline__ f2 add2(f2 a, f2 b) {
    f2 d; asm("add.rn.f32x2 %0, %1, %2;" : "=l"(d) : "l"(a), "l"(b)); return d;
}
__device__ __forceinline__ f2 fma2(f2 a, f2 b, f2 c) {
    f2 d; asm("fma.rn.f32x2 %0, %1, %2, %3;" : "=l"(d) : "l"(a), "l"(b), "l"(c)); return d;
}
__device__ __forceinline__ float sqrt_approx(float x) {
    float r; asm("sqrt.approx.f32 %0, %1;" : "=f"(r) : "f"(x)); return r;
}
__device__ __forceinline__ float expneg_approx(float x) {   // e^{-x}
    float r;
    asm("mul.f32 %0, %1, 0fBFB8AA3B;\n\tex2.approx.f32 %0, %0;" : "=f"(r) : "f"(x));
    return r;
}

// exact d2 in reference order (rescan path only)
__device__ __forceinline__ float d2_exact(const float* __restrict__ h, float h2,
                                          const float* __restrict__ c, float w2) {
    float dot = 0.f;
    #pragma unroll
    for (int d = 0; d < DN; d++) dot = fmaf(h[d], c[d], dot);
    float t = fmaf(-2.0f, dot, h2);   // == fl(h2 - fl(2*dot)), 2*dot exact
    return __fadd_rn(t, w2);
}

__device__ __forceinline__ void finish_pos(
    const float* __restrict__ h, float h2, float best0, float best1, int k0,
    float S, const f2* __restrict__ acc, int n, int l,
    const float* __restrict__ cs, const float* __restrict__ w2s,
    float* __restrict__ out, int out_size)
{
    float sq0 = __fsqrt_rn(fmaxf(best0, 1e-12f));
    float sq1 = __fsqrt_rn(fmaxf(best1, 1e-12f));
    int bk = k0;
    if (sq1 == sq0) {   // plateau tie (rare): exact first-index rule
        for (int k = 0; k < KN; k++) {
            float d2 = d2_exact(h, h2, cs + k * DN, w2s[k]);
            if (__fsqrt_rn(fmaxf(d2, 1e-12f)) == sq0) { bk = k; break; }
        }
    }

    float inv = 1.0f / S;
    float so[DN];
    #pragma unroll
    for (int i = 0; i < 8; i++) unpack2(acc[i], so[2 * i], so[2 * i + 1]);

    float4* o4 = reinterpret_cast<float4*>(out + (size_t)n * 128 + l * DN);
    #pragma unroll
    for (int j = 0; j < 4; j++) {
        float4 v;
        v.x = so[4 * j + 0] * inv;
        v.y = so[4 * j + 1] * inv;
        v.z = so[4 * j + 2] * inv;
        v.w = so[4 * j + 3] * inv;
        o4[j] = v;
    }
    if (out_size >= 2 * HN) {
        const float4* cr = reinterpret_cast<const float4*>(cs + bk * DN);
        float4* ho = reinterpret_cast<float4*>(out + HN + (size_t)n * 128 + l * DN);
        #pragma unroll
        for (int j = 0; j < 4; j++) ho[j] = cr[j];
    }
    if (out_size >= 2 * HN + NPOS * LN) {
        out[2 * HN + (size_t)n * LN + l] = (float)bk;
    }
}

template<bool DO_B>
__device__ __forceinline__ void vq_work(
    int n0, int n1, bool bvalid, int l,
    const float* __restrict__ z,
    const float* __restrict__ cs, const float* __restrict__ w2s,
    float* __restrict__ out, int out_size)
{
    const int n1c = bvalid ? n1 : n0;   // safe index for loads

    float hA[DN], hB[DN];
    {
        const int b0 = n0 >> 10,  s0 = n0 & 1023;
        const float* za = z + (size_t)b0 * (128 * 1024) + (size_t)(l * DN) * 1024 + s0;
        #pragma unroll
        for (int d = 0; d < DN; d++) hA[d] = za[(size_t)d * 1024];
        if (DO_B) {
            const int b1 = n1c >> 10, s1 = n1c & 1023;
            const float* zb = z + (size_t)b1 * (128 * 1024) + (size_t)(l * DN) * 1024 + s1;
            #pragma unroll
            for (int d = 0; d < DN; d++) hB[d] = zb[(size_t)d * 1024];
        }
    }
    float h2A = 0.f, h2B = 0.f;
    #pragma unroll
    for (int d = 0; d < DN; d++) h2A = __fadd_rn(h2A, __fmul_rn(hA[d], hA[d]));
    if (DO_B) {
        #pragma unroll
        for (int d = 0; d < DN; d++) h2B = __fadd_rn(h2B, __fmul_rn(hB[d], hB[d]));
    }

    float bA0 = 3.4e38f, bA1 = 3.4e38f, bB0 = 3.4e38f, bB1 = 3.4e38f;
    int   kA0 = 0, kB0 = 0;
    f2    S_AB = 0ull;        // packed (SA, SB); SB unused when !DO_B
    f2 accA[8], accB[8];
    #pragma unroll
    for (int i = 0; i < 8; i++) { accA[i] = 0ull; accB[i] = 0ull; }

    const ulonglong2* qp = reinterpret_cast<const ulonglong2*>(cs);

    #pragma unroll 2
    for (int k = 0; k < KN; k++) {
        ulonglong2 A = qp[k * 4 + 0];
        ulonglong2 B = qp[k * 4 + 1];
        ulonglong2 C = qp[k * 4 + 2];
        ulonglong2 D = qp[k * 4 + 3];
        float w2 = w2s[k];

        float q0,q1,q2,q3,q4,q5,q6,q7,q8,q9,q10,q11,q12,q13,q14,q15;
        unpack2(A.x, q0,  q1);  unpack2(A.y, q2,  q3);
        unpack2(B.x, q4,  q5);  unpack2(B.y, q6,  q7);
        unpack2(C.x, q8,  q9);  unpack2(C.y, q10, q11);
        unpack2(D.x, q12, q13); unpack2(D.y, q14, q15);

        // exact sequential dots (reference contraction order)
        float dA = 0.f, dB = 0.f;
        dA = fmaf(hA[0],q0,dA);   if (DO_B) dB = fmaf(hB[0],q0,dB);
        dA = fmaf(hA[1],q1,dA);   if (DO_B) dB = fmaf(hB[1],q1,dB);
        dA = fmaf(hA[2],q2,dA);   if (DO_B) dB = fmaf(hB[2],q2,dB);
        dA = fmaf(hA[3],q3,dA);   if (DO_B) dB = fmaf(hB[3],q3,dB);
        dA = fmaf(hA[4],q4,dA);   if (DO_B) dB = fmaf(hB[4],q4,dB);
        dA = fmaf(hA[5],q5,dA);   if (DO_B) dB = fmaf(hB[5],q5,dB);
        dA = fmaf(hA[6],q6,dA);   if (DO_B) dB = fmaf(hB[6],q6,dB);
        dA = fmaf(hA[7],q7,dA);   if (DO_B) dB = fmaf(hB[7],q7,dB);
        dA = fmaf(hA[8],q8,dA);   if (DO_B) dB = fmaf(hB[8],q8,dB);
        dA = fmaf(hA[9],q9,dA);   if (DO_B) dB = fmaf(hB[9],q9,dB);
        dA = fmaf(hA[10],q10,dA); if (DO_B) dB = fmaf(hB[10],q10,dB);
        dA = fmaf(hA[11],q11,dA); if (DO_B) dB = fmaf(hB[11],q11,dB);
        dA = fmaf(hA[12],q12,dA); if (DO_B) dB = fmaf(hB[12],q12,dB);
        dA = fmaf(hA[13],q13,dA); if (DO_B) dB = fmaf(hB[13],q13,dB);
        dA = fmaf(hA[14],q14,dA); if (DO_B) dB = fmaf(hB[14],q14,dB);
        dA = fmaf(hA[15],q15,dA); if (DO_B) dB = fmaf(hB[15],q15,dB);

        float d2A = __fadd_rn(fmaf(-2.0f, dA, h2A), w2);

        float oA = bA0; bool lA = d2A < bA0;
        bA0 = lA ? d2A : bA0;  kA0 = lA ? k : kA0;
        bA1 = fminf(bA1, fmaxf(oA, d2A));

        float wA = expneg_approx(sqrt_approx(fmaxf(d2A, 1e-12f)));
        f2 wpA = pack2(wA, wA);
        accA[0] = fma2(wpA, A.x, accA[0]);
        accA[1] = fma2(wpA, A.y, accA[1]);
        accA[2] = fma2(wpA, B.x, accA[2]);
        accA[3] = fma2(wpA, B.y, accA[3]);
        accA[4] = fma2(wpA, C.x, accA[4]);
        accA[5] = fma2(wpA, C.y, accA[5]);
        accA[6] = fma2(wpA, D.x, accA[6]);
        accA[7] = fma2(wpA, D.y, accA[7]);

        if (DO_B) {
            float d2B = __fadd_rn(fmaf(-2.0f, dB, h2B), w2);

            float oB = bB0; bool lB = d2B < bB0;
            bB0 = lB ? d2B : bB0;  kB0 = lB ? k : kB0;
            bB1 = fminf(bB1, fmaxf(oB, d2B));

            float wB = expneg_approx(sqrt_approx(fmaxf(d2B, 1e-12f)));
            S_AB = add2(S_AB, pack2(wA, wB));       // packed S accumulate
            f2 wpB = pack2(wB, wB);
            accB[0] = fma2(wpB, A.x, accB[0]);
            accB[1] = fma2(wpB, A.y, accB[1]);
            accB[2] = fma2(wpB, B.x, accB[2]);
            accB[3] = fma2(wpB, B.y, accB[3]);
            accB[4] = fma2(wpB, C.x, accB[4]);
            accB[5] = fma2(wpB, C.y, accB[5]);
            accB[6] = fma2(wpB, D.x, accB[6]);
            accB[7] = fma2(wpB, D.y, accB[7]);
        } else {
            S_AB = add2(S_AB, pack2(wA, 0.f));
        }
    }

    float SA, SB; unpack2(S_AB, SA, SB);
    finish_pos(hA, h2A, bA0, bA1, kA0, SA, accA, n0, l, cs, w2s, out, out_size);
    if (DO_B && bvalid)
        finish_pos(hB, h2B, bB0, bB1, kB0, SB, accB, n1, l, cs, w2s, out, out_size);
}

__global__ __launch_bounds__(128, 4)
void vq_kernel(const float* __restrict__ z,
               const float* __restrict__ codes,
               float* __restrict__ out,
               int out_size)
{
    __shared__ __align__(16) float cs[KN * DN];   // codes[l], [k][d], 32 KB
    __shared__ float w2s[KN];                     // ||codes[l][k]||^2 (ref order)

    const int l = blockIdx.y;
    const int t = threadIdx.x;

    // ---- cooperative load of codes[l] ----
    {
        const float4* cg = reinterpret_cast<const float4*>(codes + (size_t)l * KN * DN);
        float4* cs4 = reinterpret_cast<float4*>(cs);
        #pragma unroll 4
        for (int i = t; i < KN * DN / 4; i += 128) cs4[i] = cg[i];
    }
    __syncthreads();
    for (int k = t; k < KN; k += 128) {
        const float* c = cs + k * DN;
        float a = 0.f;
        #pragma unroll
        for (int d = 0; d < DN; d++) a = __fadd_rn(a, __fmul_rn(c[d], c[d]));
        w2s[k] = a;
    }
    __syncthreads();

    const int base = blockIdx.x * BLKPOS;
    const int n0 = base + t;             // always < NPOS (max 16333)
    const int n1 = base + 128 + t;       // stream B: valid iff t<94 && n1<NPOS
    const bool bvalid = (t < 94) && (n1 < NPOS);

    if (t < 96) {   // warps 0-2: dual stream
        vq_work<true>(n0, n1, bvalid, l, z, cs, w2s, out, out_size);
    } else {        // warp 3: single stream
        vq_work<false>(n0, 0, false, l, z, cs, w2s, out, out_size);
    }
}

extern "C" void kernel_launch(void* const* d_in, const int* in_sizes, int n_in,
                              void* d_out, int out_size) {
    const float* z     = (const float*)d_in[0];
    const float* codes = (const float*)d_in[1];
    float* out = (float*)d_out;

    dim3 grid(74, LN);   // 592 blocks = 148 SMs x 4 CTAs, perfectly balanced
    vq_kernel<<<grid, 128>>>(z, codes, out, out_size);
}

// round 13
// speedup vs baseline: 1.7572x; 1.0308x over previous
#include <cuda_runtime.h>
#include <cstdint>

// Shapes (fixed):
//   z:     [16, 128, 32, 32] f32   (B=16, C=128=L*D, H=W=32)
//   codes: [8, 512, 16]      f32   (L=8, K=512, D=16)
// d_out (f32): soft[16384*128] | hard[16384*128] | idx[16384*8]

#define KN   512
#define DN   16
#define LN   8
#define NPOS 16384
#define HN   (NPOS * 128)
#define BLKPOS 222               // positions per block (74 blocks/l)

typedef unsigned long long f2;  // packed f32x2

__device__ __forceinline__ f2 pack2(float lo, float hi) {
    f2 r; asm("mov.b64 %0, {%1,%2};" : "=l"(r) : "f"(lo), "f"(hi)); return r;
}
__device__ __forceinline__ void unpack2(f2 v, float& lo, float& hi) {
    asm("mov.b64 {%0,%1}, %2;" : "=f"(lo), "=f"(hi) : "l"(v));
}
__device__ __forceinline__ f2 fma2(f2 a, f2 b, f2 c) {
    f2 d; asm("fma.rn.f32x2 %0, %1, %2, %3;" : "=l"(d) : "l"(a), "l"(b), "l"(c)); return d;
}
__device__ __forceinline__ float sqrt_approx(float x) {
    float r; asm("sqrt.approx.f32 %0, %1;" : "=f"(r) : "f"(x)); return r;
}
__device__ __forceinline__ float expneg_approx(float x) {   // e^{-x}
    float r;
    asm("mul.f32 %0, %1, 0fBFB8AA3B;\n\tex2.approx.f32 %0, %0;" : "=f"(r) : "f"(x));
    return r;
}

// exact d2 in reference order (rescan path only)
__device__ __forceinline__ float d2_exact(const float* __restrict__ h, float h2,
                                          const float* __restrict__ c, float w2) {
    float dot = 0.f;
    #pragma unroll
    for (int d = 0; d < DN; d++) dot = fmaf(h[d], c[d], dot);
    float t = fmaf(-2.0f, dot, h2);   // == fl(h2 - fl(2*dot)), 2*dot exact
    return __fadd_rn(t, w2);
}

__device__ __forceinline__ void finish_pos(
    const float* __restrict__ h, float h2, float best0, float best1, int k0,
    float S, const f2* __restrict__ acc, int n, int l,
    const float* __restrict__ cs, const float* __restrict__ w2s,
    float* __restrict__ out, int out_size)
{
    float sq0 = __fsqrt_rn(fmaxf(best0, 1e-12f));
    float sq1 = __fsqrt_rn(fmaxf(best1, 1e-12f));
    int bk = k0;
    if (sq1 == sq0) {   // plateau tie (rare): exact first-index rule
        for (int k = 0; k < KN; k++) {
            float d2 = d2_exact(h, h2, cs + k * DN, w2s[k]);
            if (__fsqrt_rn(fmaxf(d2, 1e-12f)) == sq0) { bk = k; break; }
        }
    }

    float inv = 1.0f / S;
    float so[DN];
    #pragma unroll
    for (int i = 0; i < 8; i++) unpack2(acc[i], so[2 * i], so[2 * i + 1]);

    float4* o4 = reinterpret_cast<float4*>(out + (size_t)n * 128 + l * DN);
    #pragma unroll
    for (int j = 0; j < 4; j++) {
        float4 v;
        v.x = so[4 * j + 0] * inv;
        v.y = so[4 * j + 1] * inv;
        v.z = so[4 * j + 2] * inv;
        v.w = so[4 * j + 3] * inv;
        o4[j] = v;
    }
    if (out_size >= 2 * HN) {
        const float4* cr = reinterpret_cast<const float4*>(cs + bk * DN);
        float4* ho = reinterpret_cast<float4*>(out + HN + (size_t)n * 128 + l * DN);
        #pragma unroll
        for (int j = 0; j < 4; j++) ho[j] = cr[j];
    }
    if (out_size >= 2 * HN + NPOS * LN) {
        out[2 * HN + (size_t)n * LN + l] = (float)bk;
    }
}

template<bool DO_B>
__device__ __forceinline__ void vq_work(
    int n0, int n1, bool bvalid, int l,
    const float* __restrict__ z,
    const float* __restrict__ cs, const float* __restrict__ w2s,
    float* __restrict__ out, int out_size)
{
    const int n1c = bvalid ? n1 : n0;   // safe index for loads

    float hA[DN], hB[DN];
    {
        const int b0 = n0 >> 10,  s0 = n0 & 1023;
        const float* za = z + (size_t)b0 * (128 * 1024) + (size_t)(l * DN) * 1024 + s0;
        #pragma unroll
        for (int d = 0; d < DN; d++) hA[d] = za[(size_t)d * 1024];
        if (DO_B) {
            const int b1 = n1c >> 10, s1 = n1c & 1023;
            const float* zb = z + (size_t)b1 * (128 * 1024) + (size_t)(l * DN) * 1024 + s1;
            #pragma unroll
            for (int d = 0; d < DN; d++) hB[d] = zb[(size_t)d * 1024];
        }
    }
    float h2A = 0.f, h2B = 0.f;
    #pragma unroll
    for (int d = 0; d < DN; d++) h2A = __fadd_rn(h2A, __fmul_rn(hA[d], hA[d]));
    if (DO_B) {
        #pragma unroll
        for (int d = 0; d < DN; d++) h2B = __fadd_rn(h2B, __fmul_rn(hB[d], hB[d]));
    }

    float bA0 = 3.4e38f, bA1 = 3.4e38f, bB0 = 3.4e38f, bB1 = 3.4e38f;
    int   kA0 = 0, kB0 = 0;
    float SA = 0.f, SB = 0.f;
    f2 accA[8], accB[8];
    #pragma unroll
    for (int i = 0; i < 8; i++) { accA[i] = 0ull; accB[i] = 0ull; }

    const float4*     q4 = reinterpret_cast<const float4*>(cs);      // scalar view
    const ulonglong2* qp = reinterpret_cast<const ulonglong2*>(cs);  // packed view

    #pragma unroll 4
    for (int k = 0; k < KN; k++) {
        // scalar view: feeds the exact sequential dots (no unpack movs)
        float4 qa = q4[k * 4 + 0];
        float4 qb = q4[k * 4 + 1];
        float4 qc = q4[k * 4 + 2];
        float4 qd = q4[k * 4 + 3];
        // packed view: feeds the f32x2 accumulators (no pack movs)
        ulonglong2 A = qp[k * 4 + 0];
        ulonglong2 B = qp[k * 4 + 1];
        ulonglong2 C = qp[k * 4 + 2];
        ulonglong2 D = qp[k * 4 + 3];
        float w2 = w2s[k];

        // exact sequential dots (reference contraction order)
        float dA = 0.f, dB = 0.f;
        dA = fmaf(hA[0], qa.x,dA);  if (DO_B) dB = fmaf(hB[0], qa.x,dB);
        dA = fmaf(hA[1], qa.y,dA);  if (DO_B) dB = fmaf(hB[1], qa.y,dB);
        dA = fmaf(hA[2], qa.z,dA);  if (DO_B) dB = fmaf(hB[2], qa.z,dB);
        dA = fmaf(hA[3], qa.w,dA);  if (DO_B) dB = fmaf(hB[3], qa.w,dB);
        dA = fmaf(hA[4], qb.x,dA);  if (DO_B) dB = fmaf(hB[4], qb.x,dB);
        dA = fmaf(hA[5], qb.y,dA);  if (DO_B) dB = fmaf(hB[5], qb.y,dB);
        dA = fmaf(hA[6], qb.z,dA);  if (DO_B) dB = fmaf(hB[6], qb.z,dB);
        dA = fmaf(hA[7], qb.w,dA);  if (DO_B) dB = fmaf(hB[7], qb.w,dB);
        dA = fmaf(hA[8], qc.x,dA);  if (DO_B) dB = fmaf(hB[8], qc.x,dB);
        dA = fmaf(hA[9], qc.y,dA);  if (DO_B) dB = fmaf(hB[9], qc.y,dB);
        dA = fmaf(hA[10],qc.z,dA);  if (DO_B) dB = fmaf(hB[10],qc.z,dB);
        dA = fmaf(hA[11],qc.w,dA);  if (DO_B) dB = fmaf(hB[11],qc.w,dB);
        dA = fmaf(hA[12],qd.x,dA);  if (DO_B) dB = fmaf(hB[12],qd.x,dB);
        dA = fmaf(hA[13],qd.y,dA);  if (DO_B) dB = fmaf(hB[13],qd.y,dB);
        dA = fmaf(hA[14],qd.z,dA);  if (DO_B) dB = fmaf(hB[14],qd.z,dB);
        dA = fmaf(hA[15],qd.w,dA);  if (DO_B) dB = fmaf(hB[15],qd.w,dB);

        float d2A = __fadd_rn(fmaf(-2.0f, dA, h2A), w2);

        float oA = bA0; bool lA = d2A < bA0;
        bA0 = lA ? d2A : bA0;  kA0 = lA ? k : kA0;
        bA1 = fminf(bA1, fmaxf(oA, d2A));

        float wA = expneg_approx(sqrt_approx(fmaxf(d2A, 1e-12f)));
        SA += wA;
        f2 wpA = pack2(wA, wA);
        accA[0] = fma2(wpA, A.x, accA[0]);
        accA[1] = fma2(wpA, A.y, accA[1]);
        accA[2] = fma2(wpA, B.x, accA[2]);
        accA[3] = fma2(wpA, B.y, accA[3]);
        accA[4] = fma2(wpA, C.x, accA[4]);
        accA[5] = fma2(wpA, C.y, accA[5]);
        accA[6] = fma2(wpA, D.x, accA[6]);
        accA[7] = fma2(wpA, D.y, accA[7]);

        if (DO_B) {
            float d2B = __fadd_rn(fmaf(-2.0f, dB, h2B), w2);

            float oB = bB0; bool lB = d2B < bB0;
            bB0 = lB ? d2B : bB0;  kB0 = lB ? k : kB0;
            bB1 = fminf(bB1, fmaxf(oB, d2B));

            float wB = expneg_approx(sqrt_approx(fmaxf(d2B, 1e-12f)));
            SB += wB;
            f2 wpB = pack2(wB, wB);
            accB[0] = fma2(wpB, A.x, accB[0]);
            accB[1] = fma2(wpB, A.y, accB[1]);
            accB[2] = fma2(wpB, B.x, accB[2]);
            accB[3] = fma2(wpB, B.y, accB[3]);
            accB[4] = fma2(wpB, C.x, accB[4]);
            accB[5] = fma2(wpB, C.y, accB[5]);
            accB[6] = fma2(wpB, D.x, accB[6]);
            accB[7] = fma2(wpB, D.y, accB[7]);
        }
    }

    finish_pos(hA, h2A, bA0, bA1, kA0, SA, accA, n0, l, cs, w2s, out, out_size);
    if (DO_B && bvalid)
        finish_pos(hB, h2B, bB0, bB1, kB0, SB, accB, n1, l, cs, w2s, out, out_size);
}

__global__ __launch_bounds__(128, 4)
void vq_kernel(const float* __restrict__ z,
               const float* __restrict__ codes,
               float* __restrict__ out,
               int out_size)
{
    __shared__ __align__(16) float cs[KN * DN];   // codes[l], [k][d], 32 KB
    __shared__ float w2s[KN];                     // ||codes[l][k]||^2 (ref order)

    const int l = blockIdx.y;
    const int t = threadIdx.x;

    // ---- cooperative load of codes[l] ----
    {
        const float4* cg = reinterpret_cast<const float4*>(codes + (size_t)l * KN * DN);
        float4* cs4 = reinterpret_cast<float4*>(cs);
        #pragma unroll 4
        for (int i = t; i < KN * DN / 4; i += 128) cs4[i] = cg[i];
    }
    __syncthreads();
    for (int k = t; k < KN; k += 128) {
        const float* c = cs + k * DN;
        float a = 0.f;
        #pragma unroll
        for (int d = 0; d < DN; d++) a = __fadd_rn(a, __fmul_rn(c[d], c[d]));
        w2s[k] = a;
    }
    __syncthreads();

    const int base = blockIdx.x * BLKPOS;
    const int n0 = base + t;             // always < NPOS (max 16333)
    const int n1 = base + 128 + t;       // stream B: valid iff t<94 && n1<NPOS
    const bool bvalid = (t < 94) && (n1 < NPOS);

    if (t < 96) {   // warps 0-2: dual stream
        vq_work<true>(n0, n1, bvalid, l, z, cs, w2s, out, out_size);
    } else {        // warp 3: single stream
        vq_work<false>(n0, 0, false, l, z, cs, w2s, out, out_size);
    }
}

extern "C" void kernel_launch(void* const* d_in, const int* in_sizes, int n_in,
                              void* d_out, int out_size) {
    const float* z     = (const float*)d_in[0];
    const float* codes = (const float*)d_in[1];
    float* out = (float*)d_out;

    dim3 grid(74, LN);   // 592 blocks = 148 SMs x 4 CTAs, perfectly balanced
    vq_kernel<<<grid, 128>>>(z, codes, out, out_size);
}